// round 1
// baseline (speedup 1.0000x reference)
#include <cuda_runtime.h>

#define N_FULL   50000
#define NLAT     10
#define MU       32
#define BATCH    8
#define DEC_PAD  12
#define NODES    32
#define TMAIN    256

// Scratch (static __device__ arrays: no dynamic allocation allowed)
__device__ float g_encoded[BATCH * NLAT];
__device__ __align__(16) float g_decT[N_FULL * DEC_PAD];

// ---------------------------------------------------------------------------
// Kernel 1: zero the encoded accumulator + transpose decoder [n,N] -> [N,12]
// (rows padded to 48B so each row is three aligned float4s)
// ---------------------------------------------------------------------------
__global__ void prep_kernel(const float* __restrict__ decoder) {
    int p = blockIdx.x * blockDim.x + threadIdx.x;
    if (blockIdx.x == 0 && threadIdx.x < BATCH * NLAT)
        g_encoded[threadIdx.x] = 0.0f;
    if (p < N_FULL) {
        float v[DEC_PAD];
#pragma unroll
        for (int i = 0; i < NLAT; i++) v[i] = decoder[(size_t)i * N_FULL + p];
        v[10] = 0.0f; v[11] = 0.0f;
#pragma unroll
        for (int i = 0; i < DEC_PAD; i++) g_decT[(size_t)p * DEC_PAD + i] = v[i];
    }
}

// ---------------------------------------------------------------------------
// Kernel 2: encoded[b,i] = sum_j x[b,j] * enc_w[i,j]   (bias added later)
// Grid-stride, 80 accumulators/thread, warp shfl reduce, block reduce, atomics.
// ---------------------------------------------------------------------------
__global__ void encode_kernel(const float* __restrict__ x,
                              const float* __restrict__ ew) {
    int idx0   = blockIdx.x * blockDim.x + threadIdx.x;
    int stride = gridDim.x * blockDim.x;
    float acc[BATCH * NLAT];
#pragma unroll
    for (int t = 0; t < BATCH * NLAT; t++) acc[t] = 0.0f;

    for (int idx = idx0; idx < N_FULL; idx += stride) {
        float xv[BATCH], wv[NLAT];
#pragma unroll
        for (int b = 0; b < BATCH; b++) xv[b] = x[(size_t)b * N_FULL + idx];
#pragma unroll
        for (int i = 0; i < NLAT; i++) wv[i] = ew[(size_t)i * N_FULL + idx];
#pragma unroll
        for (int b = 0; b < BATCH; b++)
#pragma unroll
            for (int i = 0; i < NLAT; i++)
                acc[b * NLAT + i] = fmaf(xv[b], wv[i], acc[b * NLAT + i]);
    }

#pragma unroll
    for (int t = 0; t < BATCH * NLAT; t++) {
        float v = acc[t];
        v += __shfl_xor_sync(0xffffffffu, v, 16);
        v += __shfl_xor_sync(0xffffffffu, v, 8);
        v += __shfl_xor_sync(0xffffffffu, v, 4);
        v += __shfl_xor_sync(0xffffffffu, v, 2);
        v += __shfl_xor_sync(0xffffffffu, v, 1);
        acc[t] = v;
    }

    __shared__ float red[8][BATCH * NLAT];
    int lane = threadIdx.x & 31, warp = threadIdx.x >> 5;
    if (lane == 0) {
#pragma unroll
        for (int t = 0; t < BATCH * NLAT; t++) red[warp][t] = acc[t];
    }
    __syncthreads();
    if (threadIdx.x < BATCH * NLAT) {
        float s = 0.0f;
        int nw = blockDim.x >> 5;
        for (int w = 0; w < nw; w++) s += red[w][threadIdx.x];
        atomicAdd(&g_encoded[threadIdx.x], s);
    }
}

// ---------------------------------------------------------------------------
// Kernel 3: main. One block = NODES(32) nodes x BATCH(8) batches = 256 thr.
//
// Closed-form bubble window:
//   t_m = relu(1 - m^2 * inv2) active iff m < u = MU*w, inv2 = 1/u^2.
//   sum_m t_m          = cnt - inv2 * S2(cnt)
//   sum_m t_m * g_m    = Pg[cnt] - inv2 * Pm2[cnt]
// where cnt = min(32, floor(u)+1), Pg/Pm2 inclusive prefix sums over m.
// Prefix sums computed once per (i,p), reused by all 8 batches.
//
// SMEM layout (all keep node index j in the lane dimension -> bank == j,
// conflict-free even for the data-dependent cnt lookup):
//   G [i][m][j]  : gathered decoder vals, then in-place inclusive prefix of g
//   W2[i][m][j]  : inclusive prefix of m^2 * g
//   NB[m][j]     : neighbours transposed
// ---------------------------------------------------------------------------
__global__ void __launch_bounds__(TMAIN)
main_kernel(const float* __restrict__ enc_b,
            const float* __restrict__ bw,
            const int*   __restrict__ neigh,
            float*       __restrict__ out) {
    extern __shared__ float sm[];
    float* G  = sm;                              // NLAT*MU*NODES = 10240 floats
    float* W2 = sm + NLAT * MU * NODES;          // 10240 floats
    int*   NB = (int*)(sm + 2 * NLAT * MU * NODES); // MU*NODES ints

    const int tid  = threadIdx.x;
    const int lane = tid & 31;
    const int warp = tid >> 5;
    const int p_base = blockIdx.x * NODES;

    // ---- load neighbours tile, transposed into NB[m][j] ----
    {
        int f  = tid * 4;          // flat index over 32x32 ints
        int j  = f >> 5;
        int m0 = f & 31;
        int p  = p_base + j;
        int4 v = make_int4(0, 0, 0, 0);
        if (p < N_FULL) v = *(const int4*)(neigh + (size_t)p * MU + m0);
        NB[(m0 + 0) * NODES + j] = v.x;
        NB[(m0 + 1) * NODES + j] = v.y;
        NB[(m0 + 2) * NODES + j] = v.z;
        NB[(m0 + 3) * NODES + j] = v.w;
    }
    __syncthreads();

    // ---- Phase A: gather decoderT rows into G[i][m][j] ----
    {
        int j = lane;
#pragma unroll
        for (int mm = 0; mm < 4; mm++) {
            int m  = warp + mm * 8;
            int nb = NB[m * NODES + j];
            const float4* src = (const float4*)(g_decT + (size_t)nb * DEC_PAD);
            float4 a = src[0], b4 = src[1], c4 = src[2];
            float g[NLAT] = {a.x, a.y, a.z, a.w, b4.x, b4.y, b4.z, b4.w, c4.x, c4.y};
#pragma unroll
            for (int i = 0; i < NLAT; i++)
                G[(i * MU + m) * NODES + j] = g[i];
        }
    }
    __syncthreads();

    // ---- Phase B: inclusive prefix over m: G <- prefix(g), W2 <- prefix(m^2 g)
    for (int task = tid; task < NLAT * NODES; task += TMAIN) {
        int j = task & 31;
        int i = task >> 5;
        float pg = 0.0f, pm = 0.0f;
#pragma unroll
        for (int m = 0; m < MU; m++) {
            float v = G[(i * MU + m) * NODES + j];
            pg += v;
            pm = fmaf((float)(m * m), v, pm);
            G [(i * MU + m) * NODES + j] = pg;
            W2[(i * MU + m) * NODES + j] = pm;
        }
    }
    __syncthreads();

    // ---- Main phase: thread = (b = warp, node j = lane) ----
    const int b = warp, j = lane;
    const int p = p_base + j;
    if (p >= N_FULL) return;

    float encb[NLAT];
#pragma unroll
    for (int k = 0; k < NLAT; k++)
        encb[k] = g_encoded[b * NLAT + k] + enc_b[k];

    float acc = 0.0f;
#pragma unroll
    for (int i = 0; i < NLAT; i++) {
        // z = sum_k enc[b,k] * bw[i,k,p]  (coalesced across lanes)
        float z = 0.0f;
#pragma unroll
        for (int k = 0; k < NLAT; k++)
            z = fmaf(encb[k], bw[((size_t)(i * NLAT + k)) * N_FULL + p], z);

        float e  = __expf(-z);
        float tt = 1.0f + e;                         // = 1/w
        float u  = __fdividef((float)MU, tt);        // = MU * w
        int cnt  = min(MU, (int)u + 1);              // #active m (u > 0 always)
        float inv2 = tt * tt * (1.0f / (float)(MU * MU)); // 1/(MU*w)^2

        float Pg = G [(i * MU + (cnt - 1)) * NODES + j];
        float Pm = W2[(i * MU + (cnt - 1)) * NODES + j];
        int   c1 = cnt - 1;
        float S2 = (float)(c1 * cnt * (2 * cnt - 1)) * (1.0f / 6.0f);
        float s  = (float)cnt - inv2 * S2;
        float smv = __fdividef(fmaf(-inv2, Pm, Pg), s);
        acc = fmaf(encb[i], smv, acc);
    }
    out[(size_t)b * N_FULL + p] = acc;
}

// ---------------------------------------------------------------------------
extern "C" void kernel_launch(void* const* d_in, const int* in_sizes, int n_in,
                              void* d_out, int out_size) {
    const float* x       = (const float*)d_in[0];
    const float* enc_w   = (const float*)d_in[1];
    const float* enc_b   = (const float*)d_in[2];
    const float* decoder = (const float*)d_in[3];
    const float* bw      = (const float*)d_in[4];
    const int*   neigh   = (const int*)  d_in[5];
    float*       out     = (float*)d_out;
    (void)in_sizes; (void)n_in; (void)out_size;

    prep_kernel<<<(N_FULL + 255) / 256, 256>>>(decoder);
    encode_kernel<<<64, 256>>>(x, enc_w);

    size_t smem_bytes = (size_t)(2 * NLAT * MU * NODES) * sizeof(float)
                      + (size_t)(MU * NODES) * sizeof(int);   // 86016 B
    cudaFuncSetAttribute(main_kernel,
                         cudaFuncAttributeMaxDynamicSharedMemorySize,
                         (int)smem_bytes);
    main_kernel<<<(N_FULL + NODES - 1) / NODES, TMAIN, smem_bytes>>>(
        enc_b, bw, neigh, out);
}